// round 15
// baseline (speedup 1.0000x reference)
#include <cuda_runtime.h>
#include <math.h>

#define Hh    768
#define NB    32
#define NS    1024
#define NF    128
#define NP    256
#define NROWS (NB * NF)          // 4096
#define NC    28
#define CAP   64                 // max tokens per (b,field); Binom(1024,1/129) tail ~0
#define FG    4                  // fields per block
#define NBLK_PER_B 32            // fg blocks per batch

// output segment offsets (floats), reference return order
#define OFF_MSR   0              // (B,F,2)
#define OFF_AGG   8192           // (B,F,9)
#define OFF_MSRS  45056          // (B,F,2)
#define OFF_DIM   53248          // (B,F,2)
#define OFF_KEY   61440          // (B,F,2)
#define OFF_PAIR  69632          // (B,P,2)
#define OFF_TYPE  86016          // (B,F,7)

__device__ float g_u[NROWS * 4];        // pair partial dots
__device__ int   g_done[NB];            // per-batch tickets (self-resetting)

// ---------------------------------------------------------------------------
#define BFLY5(s) do { \
    s += __shfl_xor_sync(0xffffffffu, s, 16); \
    s += __shfl_xor_sync(0xffffffffu, s, 8);  \
    s += __shfl_xor_sync(0xffffffffu, s, 4);  \
    s += __shfl_xor_sync(0xffffffffu, s, 2);  \
    s += __shfl_xor_sync(0xffffffffu, s, 1);  \
} while (0)

// Head with NCOLS classes, native layout [768][NCOLS]. Thread tid owns h rows
// 4tid..4tid+3 -> 4*NCOLS contiguous floats at Wbase + tid*4*NCOLS.
template<int NCOLS>
__device__ __forceinline__ void head_partial(
    const float* __restrict__ Wbase, int tid, int cbase,
    const float4 v[FG], int w, int lane, float* __restrict__ sRed)
{
    float qa[4 * NCOLS];
    const float4* P = (const float4*)Wbase + tid * NCOLS;
#pragma unroll
    for (int k = 0; k < NCOLS; k++) *(float4*)(qa + 4 * k) = P[k];
#pragma unroll
    for (int c = 0; c < NCOLS; c++) {
        float s[FG];
#pragma unroll
        for (int f = 0; f < FG; f++)
            s[f] = v[f].x * qa[c]
                 + v[f].y * qa[NCOLS + c]
                 + v[f].z * qa[2 * NCOLS + c]
                 + v[f].w * qa[3 * NCOLS + c];
#pragma unroll
        for (int f = 0; f < FG; f++) BFLY5(s[f]);
        if (lane == 0) {
#pragma unroll
            for (int f = 0; f < FG; f++)
                sRed[(w * NC + cbase + c) * FG + f] = s[f];
        }
    }
}

__device__ __forceinline__ void write_lsm(float* dst, const float* l, int n)
{
    float m = l[0];
    for (int i = 1; i < n; i++) m = fmaxf(m, l[i]);
    float s = 0.f;
    for (int i = 0; i < n; i++) s += expf(l[i] - m);
    const float lse = m + logf(s);
    for (int i = 0; i < n; i++) dst[i] = l[i] - lse;
}

// ---------------------------------------------------------------------------
// k1_fused: one block per (4 fields, batch). Ballot scan (warp per field),
// WARP-PER-FIELD gather (6 independent float4/lane/row, no predication),
// smem handoff, native-weight logits, fused log_softmax + writes + pair
// partials. Last block per batch computes its 256 pair outputs (ticket).
// ---------------------------------------------------------------------------
__global__ __launch_bounds__(192, 5) void k1_fused(
    const float* __restrict__ emb, const int* __restrict__ col,
    const int* __restrict__ pidx,
    const float* __restrict__ Wmsr,  const float* __restrict__ bmsr,
    const float* __restrict__ Wagg,  const float* __restrict__ bagg,
    const float* __restrict__ Wdim,  const float* __restrict__ bdim,
    const float* __restrict__ Wmsrs, const float* __restrict__ bmsrs,
    const float* __restrict__ Wkey,  const float* __restrict__ bkey,
    const float* __restrict__ Wpair, const float* __restrict__ bpair,
    const float* __restrict__ Wtype, const float* __restrict__ btype,
    float* __restrict__ out)
{
    const int fg   = blockIdx.x;              // 0..31
    const int b    = blockIdx.y;              // 0..31
    const int tid  = threadIdx.x;             // 0..191
    const int lane = tid & 31;
    const int w    = tid >> 5;                // warp 0..5

    __shared__ int   sCol[NS];
    __shared__ int   sList[FG][CAP];
    __shared__ int   sCnt[FG];
    __shared__ float sV[FG * Hh];             // 12 KB mean handoff
    __shared__ float sRed[6 * NC * FG];
    __shared__ float sLog[FG][NC];
    __shared__ float sB[NC];
    __shared__ int   sTicket;

    // stage biases (native)
    if (tid < NC) {
        float bv = 0.f;
        if      (tid < 2)  bv = bmsr [tid];
        else if (tid < 11) bv = bagg [tid - 2];
        else if (tid < 13) bv = bdim [tid - 11];
        else if (tid < 15) bv = bmsrs[tid - 13];
        else if (tid < 17) bv = bkey [tid - 15];
        else if (tid < 24) bv = btype[tid - 17];
        sB[tid] = bv;                          // pair classes: 0 (bias in tail)
    }

    // stage col row (4 KB, coalesced)
    const int4* c4 = (const int4*)(col + b * NS);
    for (int i = tid; i < NS / 4; i += 192) ((int4*)sCol)[i] = c4[i];
    __syncthreads();

    // in-block list build + warp-per-field gather (warps 0..3)
    if (w < FG) {
        const int f = w;
        const int target = fg * FG + f + 1;   // segment 0 dropped
        int cnt = 0;
#pragma unroll 4
        for (int base = 0; base < NS; base += 32) {
            const int c = sCol[base + lane];
            const unsigned m = __ballot_sync(0xffffffffu, c == target);
            if (c == target) {
                const int pos = cnt + __popc(m & ((1u << lane) - 1u));
                if (pos < CAP) sList[f][pos] = base + lane;
            }
            cnt += __popc(m);
        }
        const int n = min(cnt, CAP);
        if (lane == 0) sCnt[f] = n;
        __syncwarp();

        // gather: warp reads full 768-dim rows; lane owns [j*32+lane]
        const float4* rowb = (const float4*)(emb + (size_t)b * NS * Hh);
        float4 acc[6];
#pragma unroll
        for (int j = 0; j < 6; j++) acc[j] = make_float4(0.f, 0.f, 0.f, 0.f);

#pragma unroll 2
        for (int i = 0; i < n; i++) {
            const float4* r = rowb + (size_t)sList[f][i] * (Hh / 4);
            float4 x[6];
#pragma unroll
            for (int j = 0; j < 6; j++) x[j] = r[j * 32 + lane];
#pragma unroll
            for (int j = 0; j < 6; j++) {
                acc[j].x += x[j].x; acc[j].y += x[j].y;
                acc[j].z += x[j].z; acc[j].w += x[j].w;
            }
        }
        const float inv = 1.0f / (float)(n > 0 ? n : 1);
        float4* vout = (float4*)(sV + f * Hh);
#pragma unroll
        for (int j = 0; j < 6; j++) {
            acc[j].x *= inv; acc[j].y *= inv; acc[j].z *= inv; acc[j].w *= inv;
            vout[j * 32 + lane] = acc[j];
        }
    }
    __syncthreads();

    // logits: thread owns h rows 4tid..4tid+3; v from smem
    float4 v[FG];
#pragma unroll
    for (int f = 0; f < FG; f++) v[f] = ((const float4*)(sV + f * Hh))[tid];

    head_partial<2>(Wmsr,         tid, 0,  v, w, lane, sRed);
    head_partial<9>(Wagg,         tid, 2,  v, w, lane, sRed);
    head_partial<2>(Wdim,         tid, 11, v, w, lane, sRed);
    head_partial<2>(Wmsrs,        tid, 13, v, w, lane, sRed);
    head_partial<2>(Wkey,         tid, 15, v, w, lane, sRed);
    head_partial<7>(Wtype,        tid, 17, v, w, lane, sRed);
    head_partial<2>(Wpair,        tid, 24, v, w, lane, sRed);   // rows 0..767
    head_partial<2>(Wpair + 1536, tid, 26, v, w, lane, sRed);   // rows 768..1535
    __syncthreads();

    // cross-warp reduce: NC*FG = 112 cells over 192 threads
    if (tid < NC * FG) {
        const int c = tid >> 2, f = tid & 3;
        float s = sB[c];
#pragma unroll
        for (int ww = 0; ww < 6; ww++) s += sRed[(ww * NC + c) * FG + f];
        sLog[f][c] = s;
    }
    __syncthreads();

    if (tid < FG) {
        const int field = fg * FG + tid;
        const int row = b * NF + field;
        float l[NC];
#pragma unroll
        for (int c = 0; c < NC; c++) l[c] = sLog[tid][c];

        write_lsm(out + OFF_MSR  + row * 2, l + 0,  2);
        write_lsm(out + OFF_AGG  + row * 9, l + 2,  9);
        write_lsm(out + OFF_MSRS + row * 2, l + 13, 2);
        write_lsm(out + OFF_DIM  + row * 2, l + 11, 2);
        write_lsm(out + OFF_KEY  + row * 2, l + 15, 2);
        write_lsm(out + OFF_TYPE + row * 7, l + 17, 7);

        float* u = g_u + row * 4;
        u[0] = l[24]; u[1] = l[25]; u[2] = l[26]; u[3] = l[27];
        __threadfence();                       // publish g_u before ticket
    }
    __syncthreads();

    // ---- pair tail: last block of this batch computes 256 pair outputs ----
    if (tid == 0) sTicket = atomicAdd(&g_done[b], 1);
    __syncthreads();
    if (sTicket == NBLK_PER_B - 1) {
        __threadfence();                       // acquire g_u from other blocks
        const float bp0 = bpair[0], bp1 = bpair[1];
        const float* ub = g_u + (size_t)b * NF * 4;
        for (int p = tid; p < NP; p += 192) {
            const int2 pr = ((const int2*)pidx)[b * NP + p];
            const float* u1 = ub + pr.x * 4;
            const float* u2 = ub + pr.y * 4;
            const float l0 = u1[0] + u2[2] + bp0;
            const float l1 = u1[1] + u2[3] + bp1;
            const float m  = fmaxf(l0, l1);
            const float lse = m + logf(expf(l0 - m) + expf(l1 - m));
            ((float2*)(out + OFF_PAIR))[b * NP + p] =
                make_float2(l0 - lse, l1 - lse);
        }
        if (tid == 0) g_done[b] = 0;           // reset for next graph replay
    }
}

// ---------------------------------------------------------------------------
extern "C" void kernel_launch(void* const* d_in, const int* in_sizes, int n_in,
                              void* d_out, int out_size)
{
    const float* emb  = (const float*)d_in[0];
    const int*   col  = (const int*)d_in[1];
    const int*   pidx = (const int*)d_in[2];
    const int wb = n_in - 14;
    const float* Wmsr  = (const float*)d_in[wb + 0];
    const float* bmsr  = (const float*)d_in[wb + 1];
    const float* Wagg  = (const float*)d_in[wb + 2];
    const float* bagg  = (const float*)d_in[wb + 3];
    const float* Wdim  = (const float*)d_in[wb + 4];
    const float* bdim  = (const float*)d_in[wb + 5];
    const float* Wmsrs = (const float*)d_in[wb + 6];
    const float* bmsrs = (const float*)d_in[wb + 7];
    const float* Wkey  = (const float*)d_in[wb + 8];
    const float* bkey  = (const float*)d_in[wb + 9];
    const float* Wpair = (const float*)d_in[wb + 10];
    const float* bpair = (const float*)d_in[wb + 11];
    const float* Wtype = (const float*)d_in[wb + 12];
    const float* btype = (const float*)d_in[wb + 13];
    float* out = (float*)d_out;

    k1_fused<<<dim3(NF / FG, NB), 192>>>(emb, col, pidx,
                                         Wmsr, bmsr, Wagg, bagg, Wdim, bdim,
                                         Wmsrs, bmsrs, Wkey, bkey,
                                         Wpair, bpair, Wtype, btype, out);
}

// round 17
// speedup vs baseline: 1.0663x; 1.0663x over previous
#include <cuda_runtime.h>
#include <math.h>

#define Hh    768
#define NB    32
#define NS    1024
#define NF    128
#define NP    256
#define NROWS (NB * NF)          // 4096
#define NC    28
#define CAP   64                 // max tokens per (b,field); Binom(1024,1/129) tail ~0
#define FG    4                  // fields per block
#define NBLK_PER_B 32            // fg blocks per batch

// output segment offsets (floats), reference return order
#define OFF_MSR   0              // (B,F,2)
#define OFF_AGG   8192           // (B,F,9)
#define OFF_MSRS  45056          // (B,F,2)
#define OFF_DIM   53248          // (B,F,2)
#define OFF_KEY   61440          // (B,F,2)
#define OFF_PAIR  69632          // (B,P,2)
#define OFF_TYPE  86016          // (B,F,7)

__device__ float g_wT[NC * Hh];         // class-major transposed weights
__device__ float g_bias[NC];
__device__ float g_u[NROWS * 4];        // pair partial dots
__device__ int   g_done[NB];            // per-batch tickets (self-resetting)

// ---------------------------------------------------------------------------
// k0w: transpose weights into g_wT. Reads coalesced (native flat order),
// writes scattered (STG fire-and-forget).
// ---------------------------------------------------------------------------
__global__ __launch_bounds__(256) void k0w(
    const float* __restrict__ Wmsr,  const float* __restrict__ bmsr,
    const float* __restrict__ Wagg,  const float* __restrict__ bagg,
    const float* __restrict__ Wdim,  const float* __restrict__ bdim,
    const float* __restrict__ Wmsrs, const float* __restrict__ bmsrs,
    const float* __restrict__ Wkey,  const float* __restrict__ bkey,
    const float* __restrict__ Wpair, const float* __restrict__ Wtype,
    const float* __restrict__ btype)
{
    const int gid = blockIdx.x * 256 + threadIdx.x;
    const int nth = gridDim.x * 256;
    for (int i = gid; i < Hh * 2; i += nth) { g_wT[(0  + (i & 1)) * Hh + (i >> 1)] = Wmsr[i]; }
    for (int i = gid; i < Hh * 9; i += nth) { int h = i / 9; g_wT[(2  + (i - h * 9)) * Hh + h] = Wagg[i]; }
    for (int i = gid; i < Hh * 2; i += nth) { g_wT[(11 + (i & 1)) * Hh + (i >> 1)] = Wdim[i]; }
    for (int i = gid; i < Hh * 2; i += nth) { g_wT[(13 + (i & 1)) * Hh + (i >> 1)] = Wmsrs[i]; }
    for (int i = gid; i < Hh * 2; i += nth) { g_wT[(15 + (i & 1)) * Hh + (i >> 1)] = Wkey[i]; }
    for (int i = gid; i < Hh * 7; i += nth) { int h = i / 7; g_wT[(17 + (i - h * 7)) * Hh + h] = Wtype[i]; }
    for (int i = gid; i < Hh * 4; i += nth) {            // Wpair: [1536][2] flat
        const int h = i >> 1, c = i & 1;                 // h in 0..1535
        const int cc = (h < Hh) ? (24 + c) : (26 + c);
        const int hh = (h < Hh) ? h : (h - Hh);
        g_wT[cc * Hh + hh] = Wpair[i];
    }
    if (gid < NC) {
        float bv = 0.f;
        if      (gid < 2)  bv = bmsr [gid];
        else if (gid < 11) bv = bagg [gid - 2];
        else if (gid < 13) bv = bdim [gid - 11];
        else if (gid < 15) bv = bmsrs[gid - 13];
        else if (gid < 17) bv = bkey [gid - 15];
        else if (gid < 24) bv = btype[gid - 17];
        g_bias[gid] = bv;               // pair classes: 0 (bias in tail)
    }
}

#define BFLY5(s) do { \
    s += __shfl_xor_sync(0xffffffffu, s, 16); \
    s += __shfl_xor_sync(0xffffffffu, s, 8);  \
    s += __shfl_xor_sync(0xffffffffu, s, 4);  \
    s += __shfl_xor_sync(0xffffffffu, s, 2);  \
    s += __shfl_xor_sync(0xffffffffu, s, 1);  \
} while (0)

__device__ __forceinline__ void write_lsm(float* dst, const float* l, int n)
{
    float m = l[0];
    for (int i = 1; i < n; i++) m = fmaxf(m, l[i]);
    float s = 0.f;
    for (int i = 0; i < n; i++) s += expf(l[i] - m);
    const float lse = m + logf(s);
    for (int i = 0; i < n; i++) dst[i] = l[i] - lse;
}

// ---------------------------------------------------------------------------
// k1_fused: one block per (4 fields, batch). Ballot scan (warp per field),
// MLP-4 interleaved gather (R14), g_wT coalesced logits, fused log_softmax
// + writes + pair partials. Last block per batch does its 256 pair outputs.
// ---------------------------------------------------------------------------
__global__ __launch_bounds__(192, 5) void k1_fused(
    const float* __restrict__ emb, const int* __restrict__ col,
    const int* __restrict__ pidx, const float* __restrict__ bpair,
    float* __restrict__ out)
{
    const int fg   = blockIdx.x;              // 0..31
    const int b    = blockIdx.y;              // 0..31
    const int tid  = threadIdx.x;             // 0..191
    const int lane = tid & 31;
    const int w    = tid >> 5;                // warp 0..5

    __shared__ int   sCol[NS];
    __shared__ int   sList[FG][CAP];
    __shared__ int   sCnt[FG];
    __shared__ float sRed[6 * NC * FG];
    __shared__ float sLog[FG][NC];
    __shared__ int   sTicket;

    // stage col row (4 KB, coalesced)
    const int4* c4 = (const int4*)(col + b * NS);
    for (int i = tid; i < NS / 4; i += 192) ((int4*)sCol)[i] = c4[i];
    __syncthreads();

    // in-block list build: warps 0..3, one field each
    if (w < FG) {
        const int f = w;
        const int target = fg * FG + f + 1;   // segment 0 dropped
        int cnt = 0;
#pragma unroll 4
        for (int base = 0; base < NS; base += 32) {
            const int c = sCol[base + lane];
            const unsigned m = __ballot_sync(0xffffffffu, c == target);
            if (c == target) {
                const int pos = cnt + __popc(m & ((1u << lane) - 1u));
                if (pos < CAP) sList[f][pos] = base + lane;
            }
            cnt += __popc(m);
        }
        if (lane == 0) sCnt[f] = min(cnt, CAP);
    }
    __syncthreads();

    // interleaved gather: one token from each of 4 fields per round
    const float4* ebase = (const float4*)(emb + (size_t)b * NS * Hh) + tid;
    int n[FG];
    int nmax = 0;
#pragma unroll
    for (int f = 0; f < FG; f++) { n[f] = sCnt[f]; nmax = max(nmax, n[f]); }

    float4 acc[FG];
#pragma unroll
    for (int f = 0; f < FG; f++) acc[f] = make_float4(0.f, 0.f, 0.f, 0.f);

#pragma unroll 1
    for (int i = 0; i < nmax; i++) {
        float4 x[FG];
#pragma unroll
        for (int f = 0; f < FG; f++) {
            x[f] = make_float4(0.f, 0.f, 0.f, 0.f);
            if (i < n[f]) x[f] = ebase[sList[f][i] * (Hh / 4)];
        }
#pragma unroll
        for (int f = 0; f < FG; f++) {
            acc[f].x += x[f].x; acc[f].y += x[f].y;
            acc[f].z += x[f].z; acc[f].w += x[f].w;
        }
    }

    float4 v[FG];
#pragma unroll
    for (int f = 0; f < FG; f++) {
        const float inv = 1.0f / (float)(n[f] > 0 ? n[f] : 1);
        v[f].x = acc[f].x * inv; v[f].y = acc[f].y * inv;
        v[f].z = acc[f].z * inv; v[f].w = acc[f].w * inv;
    }

    // logits: coalesced g_wT reads (4 wavefronts/instr), warp butterfly
    const float4* wt4 = (const float4*)g_wT;   // class c at wt4[c*192 + tid]
#pragma unroll 4
    for (int c = 0; c < NC; c++) {
        const float4 q = wt4[c * (Hh / 4) + tid];
        float s[FG];
#pragma unroll
        for (int f = 0; f < FG; f++)
            s[f] = v[f].x * q.x + v[f].y * q.y + v[f].z * q.z + v[f].w * q.w;
#pragma unroll
        for (int f = 0; f < FG; f++) BFLY5(s[f]);
        if (lane == 0) {
#pragma unroll
            for (int f = 0; f < FG; f++)
                sRed[(w * NC + c) * FG + f] = s[f];
        }
    }
    __syncthreads();

    // cross-warp reduce: NC*FG = 112 cells over 192 threads
    if (tid < NC * FG) {
        const int c = tid >> 2, f = tid & 3;
        float s = g_bias[c];
#pragma unroll
        for (int ww = 0; ww < 6; ww++) s += sRed[(ww * NC + c) * FG + f];
        sLog[f][c] = s;
    }
    __syncthreads();

    if (tid < FG) {
        const int field = fg * FG + tid;
        const int row = b * NF + field;
        float l[NC];
#pragma unroll
        for (int c = 0; c < NC; c++) l[c] = sLog[tid][c];

        write_lsm(out + OFF_MSR  + row * 2, l + 0,  2);
        write_lsm(out + OFF_AGG  + row * 9, l + 2,  9);
        write_lsm(out + OFF_MSRS + row * 2, l + 13, 2);
        write_lsm(out + OFF_DIM  + row * 2, l + 11, 2);
        write_lsm(out + OFF_KEY  + row * 2, l + 15, 2);
        write_lsm(out + OFF_TYPE + row * 7, l + 17, 7);

        float* u = g_u + row * 4;
        u[0] = l[24]; u[1] = l[25]; u[2] = l[26]; u[3] = l[27];
        __threadfence();                       // publish g_u before ticket
    }
    __syncthreads();

    // ---- pair tail: last block of this batch computes 256 pair outputs ----
    if (tid == 0) sTicket = atomicAdd(&g_done[b], 1);
    __syncthreads();
    if (sTicket == NBLK_PER_B - 1) {
        __threadfence();                       // acquire g_u from other blocks
        const float bp0 = bpair[0], bp1 = bpair[1];
        const float* ub = g_u + (size_t)b * NF * 4;
        for (int p = tid; p < NP; p += 192) {
            const int2 pr = ((const int2*)pidx)[b * NP + p];
            const float* u1 = ub + pr.x * 4;
            const float* u2 = ub + pr.y * 4;
            const float l0 = u1[0] + u2[2] + bp0;
            const float l1 = u1[1] + u2[3] + bp1;
            const float m  = fmaxf(l0, l1);
            const float lse = m + logf(expf(l0 - m) + expf(l1 - m));
            ((float2*)(out + OFF_PAIR))[b * NP + p] =
                make_float2(l0 - lse, l1 - lse);
        }
        if (tid == 0) g_done[b] = 0;           // reset for next graph replay
    }
}

// ---------------------------------------------------------------------------
extern "C" void kernel_launch(void* const* d_in, const int* in_sizes, int n_in,
                              void* d_out, int out_size)
{
    const float* emb  = (const float*)d_in[0];
    const int*   col  = (const int*)d_in[1];
    const int*   pidx = (const int*)d_in[2];
    const int wb = n_in - 14;
    const float* Wmsr  = (const float*)d_in[wb + 0];
    const float* bmsr  = (const float*)d_in[wb + 1];
    const float* Wagg  = (const float*)d_in[wb + 2];
    const float* bagg  = (const float*)d_in[wb + 3];
    const float* Wdim  = (const float*)d_in[wb + 4];
    const float* bdim  = (const float*)d_in[wb + 5];
    const float* Wmsrs = (const float*)d_in[wb + 6];
    const float* bmsrs = (const float*)d_in[wb + 7];
    const float* Wkey  = (const float*)d_in[wb + 8];
    const float* bkey  = (const float*)d_in[wb + 9];
    const float* Wpair = (const float*)d_in[wb + 10];
    const float* bpair = (const float*)d_in[wb + 11];
    const float* Wtype = (const float*)d_in[wb + 12];
    const float* btype = (const float*)d_in[wb + 13];
    float* out = (float*)d_out;

    k0w<<<42, 256>>>(Wmsr, bmsr, Wagg, bagg, Wdim, bdim,
                     Wmsrs, bmsrs, Wkey, bkey, Wpair, Wtype, btype);

    k1_fused<<<dim3(NF / FG, NB), 192>>>(emb, col, pidx, bpair, out);
}